// round 10
// baseline (speedup 1.0000x reference)
#include <cuda_runtime.h>
#include <cuda_bf16.h>
#include <cstdint>
#include <math.h>

// Problem constants
#define M_TOT 4096      // 2*N*T
#define DIM   512
#define TSPAN 16
#define NEG_INV (1.0f/31.0f)

// Device scratch (no allocs allowed)
__device__ __nv_bfloat16 g_znb[M_TOT * DIM];   // normalized z, bf16 (4 MB)
__device__ float g_rowExp[M_TOT];
__device__ float g_rowNum[M_TOT];
__device__ int   g_done;

// ---------------------------------------------------------------------------
// helpers
// ---------------------------------------------------------------------------
__device__ __forceinline__ uint32_t smem_u32(const void* p) {
    return (uint32_t)__cvta_generic_to_shared(p);
}
__device__ __forceinline__ void ldsm4(uint32_t addr, uint32_t* r) {
    asm volatile("ldmatrix.sync.aligned.m8n8.x4.shared.b16 {%0,%1,%2,%3}, [%4];"
                 : "=r"(r[0]), "=r"(r[1]), "=r"(r[2]), "=r"(r[3]) : "r"(addr));
}
__device__ __forceinline__ void mma16816(float* c, const uint32_t* a, uint32_t b0, uint32_t b1) {
    asm volatile("mma.sync.aligned.m16n8k16.row.col.f32.bf16.bf16.f32 "
                 "{%0,%1,%2,%3}, {%4,%5,%6,%7}, {%8,%9}, {%0,%1,%2,%3};"
                 : "+f"(c[0]), "+f"(c[1]), "+f"(c[2]), "+f"(c[3])
                 : "r"(a[0]), "r"(a[1]), "r"(a[2]), "r"(a[3]), "r"(b0), "r"(b1));
}
#define CP_ASYNC16(dst, src) \
    asm volatile("cp.async.cg.shared.global [%0], [%1], 16;\n" :: "r"(dst), "l"(src))
#define CP_COMMIT() asm volatile("cp.async.commit_group;\n" ::: "memory")
#define CP_WAIT2()  asm volatile("cp.async.wait_group 2;\n" ::: "memory")

// FFMA-only exp(10*a): 2^(a*14.4269504), degree-5 poly on [-0.5, 0.5]
__device__ __forceinline__ float exp10x(float a) {
    const float L = 14.4269504f;
    const float tk = __fmaf_rn(a, L, 12582912.0f);
    const int   X  = __float_as_int(tk);
    const float kf = tk - 12582912.0f;
    const float f  = __fmaf_rn(a, L, -kf);
    float p = 1.3333558e-3f;
    p = __fmaf_rn(p, f, 9.6181291e-3f);
    p = __fmaf_rn(p, f, 5.5504109e-2f);
    p = __fmaf_rn(p, f, 2.4022651e-1f);
    p = __fmaf_rn(p, f, 6.9314718e-1f);
    p = __fmaf_rn(p, f, 1.0f);
    return p * __int_as_float((X << 23) + 0x3F800000);
}

// ---------------------------------------------------------------------------
// Kernel 1 (fused prep + groupnum): one block per trajectory group (32 rows).
// Normalize fp32 -> write bf16, group sums in fp32 from smem, exact numerator
//   num_i = 10 * (zn_i . S_group - zn_i . zn_i).  Zero exp accumulators.
// ---------------------------------------------------------------------------
#define PREP_SMEM ((32 * DIM + DIM) * 4)   // 67584 B

__global__ void __launch_bounds__(256) prep_kernel(const float* __restrict__ z) {
    extern __shared__ float sm[];
    float* sZ = sm;                 // [32][DIM]
    float* S  = sm + 32 * DIM;      // [DIM]
    const int grp = blockIdx.x, tid = threadIdx.x;
    const int wid = tid >> 5, lane = tid & 31;
    if (grp == 0 && tid == 0) g_done = 0;

    // Normalize: warp w handles rows 4w..4w+3
    #pragma unroll
    for (int rr = wid * 4; rr < wid * 4 + 4; ++rr) {
        const int row = grp * TSPAN + (rr & 15) + (rr >> 4) * (M_TOT / 2);
        const float4* src = (const float4*)(z + (size_t)row * DIM);
        float4 v[4]; float ss = 0.f;
        #pragma unroll
        for (int k = 0; k < 4; ++k) {
            v[k] = src[lane + k * 32];
            ss += v[k].x*v[k].x + v[k].y*v[k].y + v[k].z*v[k].z + v[k].w*v[k].w;
        }
        #pragma unroll
        for (int o = 16; o; o >>= 1) ss += __shfl_xor_sync(0xffffffffu, ss, o);
        const float rn = 1.0f / fmaxf(sqrtf(ss), 1e-8f);
        __nv_bfloat162* dst = (__nv_bfloat162*)(g_znb + (size_t)row * DIM);
        #pragma unroll
        for (int k = 0; k < 4; ++k) {
            const int idx = lane + k * 32;
            const float x0 = v[k].x*rn, x1 = v[k].y*rn, x2 = v[k].z*rn, x3 = v[k].w*rn;
            float* d = sZ + rr * DIM + idx * 4;
            d[0] = x0; d[1] = x1; d[2] = x2; d[3] = x3;
            dst[idx*2 + 0] = __floats2bfloat162_rn(x0, x1);
            dst[idx*2 + 1] = __floats2bfloat162_rn(x2, x3);
        }
    }
    __syncthreads();

    // Group sum S[d] (each thread 2 dims); zero exp accumulators
    {
        float s0 = 0.f, s1 = 0.f;
        #pragma unroll
        for (int r = 0; r < 32; ++r) {
            s0 += sZ[r * DIM + tid * 2];
            s1 += sZ[r * DIM + tid * 2 + 1];
        }
        S[tid * 2] = s0; S[tid * 2 + 1] = s1;
    }
    if (tid < 32) {
        const int row = grp * TSPAN + (tid & 15) + (tid >> 4) * (M_TOT / 2);
        g_rowExp[row] = 0.f;
    }
    __syncthreads();

    // Numerator per row (exact fp32)
    #pragma unroll
    for (int rr = wid * 4; rr < wid * 4 + 4; ++rr) {
        const int row = grp * TSPAN + (rr & 15) + (rr >> 4) * (M_TOT / 2);
        float d1 = 0.f, d2 = 0.f;
        const float4* zr = (const float4*)(sZ + rr * DIM);
        const float4* sr = (const float4*)S;
        #pragma unroll
        for (int j = 0; j < 4; ++j) {
            const float4 a = zr[lane + j * 32];
            const float4 b = sr[lane + j * 32];
            d1 += a.x*b.x + a.y*b.y + a.z*b.z + a.w*b.w;
            d2 += a.x*a.x + a.y*a.y + a.z*a.z + a.w*a.w;
        }
        #pragma unroll
        for (int o = 16; o; o >>= 1) {
            d1 += __shfl_xor_sync(0xffffffffu, d1, o);
            d2 += __shfl_xor_sync(0xffffffffu, d2, o);
        }
        if (lane == 0) g_rowNum[row] = 10.0f * (d1 - d2);
    }
}

// ---------------------------------------------------------------------------
// Kernel 2: bf16 symmetric fused GEMM + exp-sum + last-block finalize.
// 528 upper-triangular 128x128 tiles. 3-stage cp.async pipeline, K-chunks
// of 64, R3-proven loop structure (prefetch -> commit -> wait2 -> sync ->
// compute -> sync).
// ---------------------------------------------------------------------------
#define BT 128
#define KC 64
#define NCHUNK (DIM / KC)                  // 8
#define STAGE_BYTES 32768                  // A 16KB + B 16KB per stage
#define SMEM_BYTES  (3 * STAGE_BYTES)      // 98304

__global__ void __launch_bounds__(256, 2) gemm_kernel(float* __restrict__ out) {
    extern __shared__ __align__(16) unsigned char smem[];
    __shared__ float sRow[BT], sCol[BT];
    __shared__ bool sLast;
    __shared__ float sRed[8];

    // Decode upper-triangular tile index: f(b) = b*(65-b)/2
    int idx = blockIdx.x;
    int bi = (int)(32.5f - sqrtf(1056.25f - 2.0f * (float)idx));
    if (bi < 0) bi = 0; if (bi > 31) bi = 31;
    while (bi * (65 - bi) / 2 > idx) --bi;
    while ((bi + 1) * (64 - bi) / 2 <= idx) ++bi;
    const int bj = bi + (idx - bi * (65 - bi) / 2);
    const bool diag = (bi == bj);
    const int rowBase = bi * BT, colBase = bj * BT;

    const int tid = threadIdx.x, lane = tid & 31, wid = tid >> 5;
    const int warp_m = wid & 1;        // 2 x 64 rows
    const int warp_n = wid >> 1;       // 4 x 32 cols
    const uint32_t sbase = smem_u32(smem);

    // Loader: 2 threads per row, 4 x 16B units each; swizzled 128B rows
    const int lr = tid >> 1;
    const int lu = (tid & 1) * 4;
    const __nv_bfloat16* gA = g_znb + (size_t)(rowBase + lr) * DIM + lu * 8;
    const __nv_bfloat16* gB = g_znb + (size_t)(colBase + lr) * DIM + lu * 8;
    uint32_t dstU[4];
    #pragma unroll
    for (int u = 0; u < 4; ++u)
        dstU[u] = sbase + lr * 128 + (((lu + u) ^ (lr & 7)) << 4);

    float acc[4][4][4];
    #pragma unroll
    for (int a = 0; a < 4; ++a)
        #pragma unroll
        for (int b = 0; b < 4; ++b)
            #pragma unroll
            for (int i = 0; i < 4; ++i) acc[a][b][i] = 0.f;

    // Prologue: stage chunks 0, 1
    #pragma unroll
    for (int s = 0; s < 2; ++s) {
        const uint32_t so = s * STAGE_BYTES;
        #pragma unroll
        for (int u = 0; u < 4; ++u) CP_ASYNC16(dstU[u] + so,         gA + s * KC + u * 8);
        #pragma unroll
        for (int u = 0; u < 4; ++u) CP_ASYNC16(dstU[u] + so + 16384, gB + s * KC + u * 8);
        CP_COMMIT();
    }

    // Main loop (R3 structure): prefetch first, commit every iter, wait2.
    for (int ch = 0; ch < NCHUNK; ++ch) {
        if (ch + 2 < NCHUNK) {
            const uint32_t so = ((ch + 2) % 3) * STAGE_BYTES;
            #pragma unroll
            for (int u = 0; u < 4; ++u) CP_ASYNC16(dstU[u] + so,         gA + (ch + 2) * KC + u * 8);
            #pragma unroll
            for (int u = 0; u < 4; ++u) CP_ASYNC16(dstU[u] + so + 16384, gB + (ch + 2) * KC + u * 8);
        }
        CP_COMMIT();            // every iter -> uniform wait bound
        CP_WAIT2();             // chunk ch resident
        __syncthreads();

        const uint32_t Ab = sbase + (ch % 3) * STAGE_BYTES;
        const uint32_t Bb = Ab + 16384;
        #pragma unroll
        for (int ks = 0; ks < 4; ++ks) {
            uint32_t afr[4][4], bfr[2][4];
            #pragma unroll
            for (int mt = 0; mt < 4; ++mt) {
                const int m = warp_m * 64 + mt * 16 + (lane & 15);
                const int u = ks * 2 + (lane >> 4);
                ldsm4(Ab + m * 128 + ((u ^ (m & 7)) << 4), afr[mt]);
            }
            #pragma unroll
            for (int np = 0; np < 2; ++np) {
                const int n = warp_n * 32 + np * 16 + ((lane >> 4) << 3) + (lane & 7);
                const int u = ks * 2 + ((lane >> 3) & 1);
                ldsm4(Bb + n * 128 + ((u ^ (n & 7)) << 4), bfr[np]);
            }
            #pragma unroll
            for (int mt = 0; mt < 4; ++mt)
                #pragma unroll
                for (int np = 0; np < 2; ++np) {
                    mma16816(acc[mt][np * 2 + 0], afr[mt], bfr[np][0], bfr[np][1]);
                    mma16816(acc[mt][np * 2 + 1], afr[mt], bfr[np][2], bfr[np][3]);
                }
        }
        __syncthreads();        // protect stage about to be overwritten
    }

    // ---- Epilogue: exp + row sums (and col sums for off-diagonal tiles) ----
    const int gq = lane >> 2, tq = lane & 3;
    float accRow[4][2], accCol[4][2];
    #pragma unroll
    for (int a = 0; a < 4; ++a) { accRow[a][0]=accRow[a][1]=0.f; accCol[a][0]=accCol[a][1]=0.f; }

    #pragma unroll
    for (int mt = 0; mt < 4; ++mt)
        #pragma unroll
        for (int nn = 0; nn < 4; ++nn)
            #pragma unroll
            for (int i = 0; i < 4; ++i) {
                float e = exp10x(acc[mt][nn][i]);
                if (diag) {
                    const int dR = warp_m * 64 + mt * 16 + gq + (i >> 1) * 8;
                    const int dC = warp_n * 32 + nn * 8 + tq * 2 + (i & 1);
                    if (dR == dC) e = 0.f;
                }
                accRow[mt][i >> 1] += e;
                accCol[nn][i & 1]  += e;
            }

    #pragma unroll
    for (int o = 1; o <= 2; o <<= 1)
        #pragma unroll
        for (int mt = 0; mt < 4; ++mt) {
            accRow[mt][0] += __shfl_xor_sync(0xffffffffu, accRow[mt][0], o);
            accRow[mt][1] += __shfl_xor_sync(0xffffffffu, accRow[mt][1], o);
        }
    if (!diag) {
        #pragma unroll
        for (int o = 4; o <= 16; o <<= 1)
            #pragma unroll
            for (int nn = 0; nn < 4; ++nn) {
                accCol[nn][0] += __shfl_xor_sync(0xffffffffu, accCol[nn][0], o);
                accCol[nn][1] += __shfl_xor_sync(0xffffffffu, accCol[nn][1], o);
            }
    }

    __syncthreads();
    if (tid < BT) { sRow[tid] = 0.f; sCol[tid] = 0.f; }
    __syncthreads();
    if (tq == 0) {
        #pragma unroll
        for (int mt = 0; mt < 4; ++mt)
            #pragma unroll
            for (int ih = 0; ih < 2; ++ih)
                atomicAdd(&sRow[warp_m * 64 + mt * 16 + gq + ih * 8], accRow[mt][ih]);
    }
    if (!diag && gq == 0) {
        #pragma unroll
        for (int nn = 0; nn < 4; ++nn)
            #pragma unroll
            for (int j = 0; j < 2; ++j)
                atomicAdd(&sCol[warp_n * 32 + nn * 8 + tq * 2 + j], accCol[nn][j]);
    }
    __syncthreads();
    if (tid < BT) {
        atomicAdd(&g_rowExp[rowBase + tid], sRow[tid]);
        if (!diag) atomicAdd(&g_rowExp[colBase + tid], sCol[tid]);
    }

    // ---- Last-block finalize: loss = -mean(num/31 - log(expsum)) ----
    if (tid == 0) {
        __threadfence();
        sLast = (atomicAdd(&g_done, 1) == 527);
    }
    __syncthreads();
    if (sLast) {
        float s = 0.f;
        #pragma unroll
        for (int k = 0; k < M_TOT / 256; ++k) {
            const int r = tid + k * 256;
            s += __ldcg(&g_rowNum[r]) * NEG_INV - __logf(__ldcg(&g_rowExp[r]));
        }
        #pragma unroll
        for (int o = 16; o; o >>= 1) s += __shfl_xor_sync(0xffffffffu, s, o);
        if (lane == 0) sRed[wid] = s;
        __syncthreads();
        if (tid == 0) {
            float v = 0.f;
            #pragma unroll
            for (int w = 0; w < 8; ++w) v += sRed[w];
            out[0] = -v / (float)M_TOT;
        }
    }
}

// ---------------------------------------------------------------------------
extern "C" void kernel_launch(void* const* d_in, const int* in_sizes, int n_in,
                              void* d_out, int out_size) {
    const float* z = (const float*)d_in[0];
    if (n_in > 1 && in_sizes[0] != M_TOT * DIM) z = (const float*)d_in[1];

    cudaFuncSetAttribute(prep_kernel, cudaFuncAttributeMaxDynamicSharedMemorySize, PREP_SMEM);
    cudaFuncSetAttribute(gemm_kernel, cudaFuncAttributeMaxDynamicSharedMemorySize, SMEM_BYTES);

    prep_kernel<<<128, 256, PREP_SMEM>>>(z);
    gemm_kernel<<<528, 256, SMEM_BYTES>>>((float*)d_out);
}

// round 11
// speedup vs baseline: 1.0278x; 1.0278x over previous
#include <cuda_runtime.h>
#include <cuda_bf16.h>
#include <cstdint>
#include <math.h>

// Problem constants
#define M_TOT 4096      // 2*N*T
#define DIM   512
#define TSPAN 16
#define NEG_INV (1.0f/31.0f)

// Device scratch (no allocs allowed)
__device__ __nv_bfloat16 g_znb[M_TOT * DIM];   // normalized z, bf16 (4 MB)
__device__ float g_rowExp[M_TOT];
__device__ float g_rowNum[M_TOT];
__device__ int   g_done;

// ---------------------------------------------------------------------------
// helpers
// ---------------------------------------------------------------------------
__device__ __forceinline__ uint32_t smem_u32(const void* p) {
    return (uint32_t)__cvta_generic_to_shared(p);
}
__device__ __forceinline__ void ldsm4(uint32_t addr, uint32_t* r) {
    asm volatile("ldmatrix.sync.aligned.m8n8.x4.shared.b16 {%0,%1,%2,%3}, [%4];"
                 : "=r"(r[0]), "=r"(r[1]), "=r"(r[2]), "=r"(r[3]) : "r"(addr));
}
__device__ __forceinline__ void mma16816(float* c, const uint32_t* a, uint32_t b0, uint32_t b1) {
    asm volatile("mma.sync.aligned.m16n8k16.row.col.f32.bf16.bf16.f32 "
                 "{%0,%1,%2,%3}, {%4,%5,%6,%7}, {%8,%9}, {%0,%1,%2,%3};"
                 : "+f"(c[0]), "+f"(c[1]), "+f"(c[2]), "+f"(c[3])
                 : "r"(a[0]), "r"(a[1]), "r"(a[2]), "r"(a[3]), "r"(b0), "r"(b1));
}
#define CP_ASYNC16(dst, src) \
    asm volatile("cp.async.cg.shared.global [%0], [%1], 16;\n" :: "r"(dst), "l"(src))
#define CP_COMMIT() asm volatile("cp.async.commit_group;\n" ::: "memory")
#define CP_WAIT2()  asm volatile("cp.async.wait_group 2;\n" ::: "memory")

// FFMA-only exp(10*a): 2^(a*14.4269504), degree-5 poly on [-0.5, 0.5]
__device__ __forceinline__ float exp10x(float a) {
    const float L = 14.4269504f;
    const float tk = __fmaf_rn(a, L, 12582912.0f);
    const int   X  = __float_as_int(tk);
    const float kf = tk - 12582912.0f;
    const float f  = __fmaf_rn(a, L, -kf);
    float p = 1.3333558e-3f;
    p = __fmaf_rn(p, f, 9.6181291e-3f);
    p = __fmaf_rn(p, f, 5.5504109e-2f);
    p = __fmaf_rn(p, f, 2.4022651e-1f);
    p = __fmaf_rn(p, f, 6.9314718e-1f);
    p = __fmaf_rn(p, f, 1.0f);
    return p * __int_as_float((X << 23) + 0x3F800000);
}

// ---------------------------------------------------------------------------
// Kernel 1 (fused prep + groupnum): one block per trajectory group (32 rows).
// Normalize fp32 -> write bf16, group sums in fp32 from smem, exact numerator
//   num_i = 10 * (zn_i . S_group - zn_i . zn_i).  Zero exp accumulators.
// ---------------------------------------------------------------------------
#define PREP_SMEM ((32 * DIM + DIM) * 4)   // 67584 B

__global__ void __launch_bounds__(256) prep_kernel(const float* __restrict__ z) {
    extern __shared__ float sm[];
    float* sZ = sm;                 // [32][DIM]
    float* S  = sm + 32 * DIM;      // [DIM]
    const int grp = blockIdx.x, tid = threadIdx.x;
    const int wid = tid >> 5, lane = tid & 31;
    if (grp == 0 && tid == 0) g_done = 0;

    // Normalize: warp w handles rows 4w..4w+3
    #pragma unroll
    for (int rr = wid * 4; rr < wid * 4 + 4; ++rr) {
        const int row = grp * TSPAN + (rr & 15) + (rr >> 4) * (M_TOT / 2);
        const float4* src = (const float4*)(z + (size_t)row * DIM);
        float4 v[4]; float ss = 0.f;
        #pragma unroll
        for (int k = 0; k < 4; ++k) {
            v[k] = src[lane + k * 32];
            ss += v[k].x*v[k].x + v[k].y*v[k].y + v[k].z*v[k].z + v[k].w*v[k].w;
        }
        #pragma unroll
        for (int o = 16; o; o >>= 1) ss += __shfl_xor_sync(0xffffffffu, ss, o);
        const float rn = 1.0f / fmaxf(sqrtf(ss), 1e-8f);
        __nv_bfloat162* dst = (__nv_bfloat162*)(g_znb + (size_t)row * DIM);
        #pragma unroll
        for (int k = 0; k < 4; ++k) {
            const int idx = lane + k * 32;
            const float x0 = v[k].x*rn, x1 = v[k].y*rn, x2 = v[k].z*rn, x3 = v[k].w*rn;
            float* d = sZ + rr * DIM + idx * 4;
            d[0] = x0; d[1] = x1; d[2] = x2; d[3] = x3;
            dst[idx*2 + 0] = __floats2bfloat162_rn(x0, x1);
            dst[idx*2 + 1] = __floats2bfloat162_rn(x2, x3);
        }
    }
    __syncthreads();

    // Group sum S[d] (each thread 2 dims); zero exp accumulators
    {
        float s0 = 0.f, s1 = 0.f;
        #pragma unroll
        for (int r = 0; r < 32; ++r) {
            s0 += sZ[r * DIM + tid * 2];
            s1 += sZ[r * DIM + tid * 2 + 1];
        }
        S[tid * 2] = s0; S[tid * 2 + 1] = s1;
    }
    if (tid < 32) {
        const int row = grp * TSPAN + (tid & 15) + (tid >> 4) * (M_TOT / 2);
        g_rowExp[row] = 0.f;
    }
    __syncthreads();

    // Numerator per row (exact fp32)
    #pragma unroll
    for (int rr = wid * 4; rr < wid * 4 + 4; ++rr) {
        const int row = grp * TSPAN + (rr & 15) + (rr >> 4) * (M_TOT / 2);
        float d1 = 0.f, d2 = 0.f;
        const float4* zr = (const float4*)(sZ + rr * DIM);
        const float4* sr = (const float4*)S;
        #pragma unroll
        for (int j = 0; j < 4; ++j) {
            const float4 a = zr[lane + j * 32];
            const float4 b = sr[lane + j * 32];
            d1 += a.x*b.x + a.y*b.y + a.z*b.z + a.w*b.w;
            d2 += a.x*a.x + a.y*a.y + a.z*a.z + a.w*a.w;
        }
        #pragma unroll
        for (int o = 16; o; o >>= 1) {
            d1 += __shfl_xor_sync(0xffffffffu, d1, o);
            d2 += __shfl_xor_sync(0xffffffffu, d2, o);
        }
        if (lane == 0) g_rowNum[row] = 10.0f * (d1 - d2);
    }
}

// ---------------------------------------------------------------------------
// Kernel 2: bf16 symmetric fused GEMM + exp-sum + last-block finalize.
// 2080 upper-triangular 64x64 tiles, 4 CTAs/SM (64-reg cap). 3-stage
// cp.async pipeline, K-chunks of 64.
// ---------------------------------------------------------------------------
#define BT 64
#define NTILE 64                           // M_TOT / BT
#define NBLK  2080                         // NTILE*(NTILE+1)/2
#define KC 64
#define NCHUNK (DIM / KC)                  // 8
#define STAGE_BYTES 16384                  // A 8KB + B 8KB per stage
#define SMEM_BYTES  (3 * STAGE_BYTES)      // 49152

__global__ void __launch_bounds__(256, 4) gemm_kernel(float* __restrict__ out) {
    extern __shared__ __align__(16) unsigned char smem[];
    __shared__ float sRow[BT], sCol[BT];
    __shared__ bool sLast;
    __shared__ float sRed[8];

    // Decode upper-triangular tile index: f(b) = b*(2*NTILE+1-b)/2
    int idx = blockIdx.x;
    int bi = (int)(64.5f - sqrtf(4160.25f - 2.0f * (float)idx));
    if (bi < 0) bi = 0; if (bi > NTILE - 1) bi = NTILE - 1;
    while (bi * (129 - bi) / 2 > idx) --bi;
    while ((bi + 1) * (128 - bi) / 2 <= idx) ++bi;
    const int bj = bi + (idx - bi * (129 - bi) / 2);
    const bool diag = (bi == bj);
    const int rowBase = bi * BT, colBase = bj * BT;

    const int tid = threadIdx.x, lane = tid & 31, wid = tid >> 5;
    const int warp_m = wid & 1;        // 2 x 32 rows
    const int warp_n = wid >> 1;       // 4 x 16 cols
    const uint32_t sbase = smem_u32(smem);

    // Loader: 4 threads per row, 2 x 16B units each; swizzled 128B rows
    const int lr = tid >> 2;                    // 0..63
    const int lu = (tid & 3) * 2;               // 0,2,4,6
    const __nv_bfloat16* gA = g_znb + (size_t)(rowBase + lr) * DIM + lu * 8;
    const __nv_bfloat16* gB = g_znb + (size_t)(colBase + lr) * DIM + lu * 8;
    uint32_t dstU[2];
    #pragma unroll
    for (int u = 0; u < 2; ++u)
        dstU[u] = sbase + lr * 128 + (((lu + u) ^ (lr & 7)) << 4);

    float acc[2][2][4];
    #pragma unroll
    for (int a = 0; a < 2; ++a)
        #pragma unroll
        for (int b = 0; b < 2; ++b)
            #pragma unroll
            for (int i = 0; i < 4; ++i) acc[a][b][i] = 0.f;

    // Prologue: stage chunks 0, 1
    #pragma unroll
    for (int s = 0; s < 2; ++s) {
        const uint32_t so = s * STAGE_BYTES;
        #pragma unroll
        for (int u = 0; u < 2; ++u) CP_ASYNC16(dstU[u] + so,        gA + s * KC + u * 8);
        #pragma unroll
        for (int u = 0; u < 2; ++u) CP_ASYNC16(dstU[u] + so + 8192, gB + s * KC + u * 8);
        CP_COMMIT();
    }

    // Main loop: prefetch first, commit every iter, wait_group 2.
    for (int ch = 0; ch < NCHUNK; ++ch) {
        if (ch + 2 < NCHUNK) {
            const uint32_t so = ((ch + 2) % 3) * STAGE_BYTES;
            #pragma unroll
            for (int u = 0; u < 2; ++u) CP_ASYNC16(dstU[u] + so,        gA + (ch + 2) * KC + u * 8);
            #pragma unroll
            for (int u = 0; u < 2; ++u) CP_ASYNC16(dstU[u] + so + 8192, gB + (ch + 2) * KC + u * 8);
        }
        CP_COMMIT();
        CP_WAIT2();
        __syncthreads();

        const uint32_t Ab = sbase + (ch % 3) * STAGE_BYTES;
        const uint32_t Bb = Ab + 8192;
        #pragma unroll
        for (int ks = 0; ks < 4; ++ks) {
            uint32_t afr[2][4], bfr[4];
            #pragma unroll
            for (int mt = 0; mt < 2; ++mt) {
                const int m = warp_m * 32 + mt * 16 + (lane & 15);
                const int u = ks * 2 + (lane >> 4);
                ldsm4(Ab + m * 128 + ((u ^ (m & 7)) << 4), afr[mt]);
            }
            {
                const int n = warp_n * 16 + ((lane >> 4) << 3) + (lane & 7);
                const int u = ks * 2 + ((lane >> 3) & 1);
                ldsm4(Bb + n * 128 + ((u ^ (n & 7)) << 4), bfr);
            }
            #pragma unroll
            for (int mt = 0; mt < 2; ++mt) {
                mma16816(acc[mt][0], afr[mt], bfr[0], bfr[1]);
                mma16816(acc[mt][1], afr[mt], bfr[2], bfr[3]);
            }
        }
        __syncthreads();
    }

    // ---- Epilogue: exp + row sums (and col sums for off-diagonal tiles) ----
    const int gq = lane >> 2, tq = lane & 3;
    float accRow[2][2], accCol[2][2];
    #pragma unroll
    for (int a = 0; a < 2; ++a) { accRow[a][0]=accRow[a][1]=0.f; accCol[a][0]=accCol[a][1]=0.f; }

    #pragma unroll
    for (int mt = 0; mt < 2; ++mt)
        #pragma unroll
        for (int nn = 0; nn < 2; ++nn)
            #pragma unroll
            for (int i = 0; i < 4; ++i) {
                float e = exp10x(acc[mt][nn][i]);
                if (diag) {
                    const int dR = warp_m * 32 + mt * 16 + gq + (i >> 1) * 8;
                    const int dC = warp_n * 16 + nn * 8 + tq * 2 + (i & 1);
                    if (dR == dC) e = 0.f;
                }
                accRow[mt][i >> 1] += e;
                accCol[nn][i & 1]  += e;
            }

    #pragma unroll
    for (int o = 1; o <= 2; o <<= 1)
        #pragma unroll
        for (int mt = 0; mt < 2; ++mt) {
            accRow[mt][0] += __shfl_xor_sync(0xffffffffu, accRow[mt][0], o);
            accRow[mt][1] += __shfl_xor_sync(0xffffffffu, accRow[mt][1], o);
        }
    if (!diag) {
        #pragma unroll
        for (int o = 4; o <= 16; o <<= 1)
            #pragma unroll
            for (int nn = 0; nn < 2; ++nn) {
                accCol[nn][0] += __shfl_xor_sync(0xffffffffu, accCol[nn][0], o);
                accCol[nn][1] += __shfl_xor_sync(0xffffffffu, accCol[nn][1], o);
            }
    }

    __syncthreads();
    if (tid < BT) { sRow[tid] = 0.f; sCol[tid] = 0.f; }
    __syncthreads();
    if (tq == 0) {
        #pragma unroll
        for (int mt = 0; mt < 2; ++mt)
            #pragma unroll
            for (int ih = 0; ih < 2; ++ih)
                atomicAdd(&sRow[warp_m * 32 + mt * 16 + gq + ih * 8], accRow[mt][ih]);
    }
    if (!diag && gq == 0) {
        #pragma unroll
        for (int nn = 0; nn < 2; ++nn)
            #pragma unroll
            for (int j = 0; j < 2; ++j)
                atomicAdd(&sCol[warp_n * 16 + nn * 8 + tq * 2 + j], accCol[nn][j]);
    }
    __syncthreads();
    if (tid < BT) {
        atomicAdd(&g_rowExp[rowBase + tid], sRow[tid]);
        if (!diag) atomicAdd(&g_rowExp[colBase + tid], sCol[tid]);
    }

    // ---- Last-block finalize: loss = -mean(num/31 - log(expsum)) ----
    if (tid == 0) {
        __threadfence();
        sLast = (atomicAdd(&g_done, 1) == NBLK - 1);
    }
    __syncthreads();
    if (sLast) {
        float s = 0.f;
        #pragma unroll
        for (int k = 0; k < M_TOT / 256; ++k) {
            const int r = tid + k * 256;
            s += __ldcg(&g_rowNum[r]) * NEG_INV - __logf(__ldcg(&g_rowExp[r]));
        }
        #pragma unroll
        for (int o = 16; o; o >>= 1) s += __shfl_xor_sync(0xffffffffu, s, o);
        if (lane == 0) sRed[wid] = s;
        __syncthreads();
        if (tid == 0) {
            float v = 0.f;
            #pragma unroll
            for (int w = 0; w < 8; ++w) v += sRed[w];
            out[0] = -v / (float)M_TOT;
        }
    }
}

// ---------------------------------------------------------------------------
extern "C" void kernel_launch(void* const* d_in, const int* in_sizes, int n_in,
                              void* d_out, int out_size) {
    const float* z = (const float*)d_in[0];
    if (n_in > 1 && in_sizes[0] != M_TOT * DIM) z = (const float*)d_in[1];

    cudaFuncSetAttribute(prep_kernel, cudaFuncAttributeMaxDynamicSharedMemorySize, PREP_SMEM);
    cudaFuncSetAttribute(gemm_kernel, cudaFuncAttributeMaxDynamicSharedMemorySize, SMEM_BYTES);

    prep_kernel<<<128, 256, PREP_SMEM>>>(z);
    gemm_kernel<<<NBLK, 256, SMEM_BYTES>>>((float*)d_out);
}

// round 12
// speedup vs baseline: 1.2406x; 1.2071x over previous
#include <cuda_runtime.h>
#include <cuda_bf16.h>
#include <cstdint>
#include <math.h>

// Problem constants
#define M_TOT 4096      // 2*N*T
#define DIM   512
#define TSPAN 16
#define NEG_INV (1.0f/31.0f)

// Device scratch (no allocs allowed)
__device__ __nv_bfloat16 g_znb[M_TOT * DIM];   // normalized z, bf16 (4 MB)
__device__ float g_rowExp[M_TOT];
__device__ float g_rowNum[M_TOT];

// ---------------------------------------------------------------------------
// helpers
// ---------------------------------------------------------------------------
__device__ __forceinline__ uint32_t smem_u32(const void* p) {
    return (uint32_t)__cvta_generic_to_shared(p);
}
__device__ __forceinline__ void ldsm4(uint32_t addr, uint32_t* r) {
    asm volatile("ldmatrix.sync.aligned.m8n8.x4.shared.b16 {%0,%1,%2,%3}, [%4];"
                 : "=r"(r[0]), "=r"(r[1]), "=r"(r[2]), "=r"(r[3]) : "r"(addr));
}
__device__ __forceinline__ void mma16816(float* c, const uint32_t* a, uint32_t b0, uint32_t b1) {
    asm volatile("mma.sync.aligned.m16n8k16.row.col.f32.bf16.bf16.f32 "
                 "{%0,%1,%2,%3}, {%4,%5,%6,%7}, {%8,%9}, {%0,%1,%2,%3};"
                 : "+f"(c[0]), "+f"(c[1]), "+f"(c[2]), "+f"(c[3])
                 : "r"(a[0]), "r"(a[1]), "r"(a[2]), "r"(a[3]), "r"(b0), "r"(b1));
}
#define CP_ASYNC16(dst, src) \
    asm volatile("cp.async.cg.shared.global [%0], [%1], 16;\n" :: "r"(dst), "l"(src))
#define CP_COMMIT() asm volatile("cp.async.commit_group;\n" ::: "memory")
#define CP_WAIT2()  asm volatile("cp.async.wait_group 2;\n" ::: "memory")

// FFMA-only exp(10*a): 2^(a*14.4269504), degree-5 poly on [-0.5, 0.5]
__device__ __forceinline__ float exp10x(float a) {
    const float L = 14.4269504f;
    const float tk = __fmaf_rn(a, L, 12582912.0f);
    const int   X  = __float_as_int(tk);
    const float kf = tk - 12582912.0f;
    const float f  = __fmaf_rn(a, L, -kf);
    float p = 1.3333558e-3f;
    p = __fmaf_rn(p, f, 9.6181291e-3f);
    p = __fmaf_rn(p, f, 5.5504109e-2f);
    p = __fmaf_rn(p, f, 2.4022651e-1f);
    p = __fmaf_rn(p, f, 6.9314718e-1f);
    p = __fmaf_rn(p, f, 1.0f);
    return p * __int_as_float((X << 23) + 0x3F800000);
}

// ---------------------------------------------------------------------------
// Kernel 1 (fused prep + groupnum): one block per trajectory group (32 rows).
// Normalize fp32 -> write bf16, group sums in fp32 from smem, exact numerator
//   num_i = 10 * (zn_i . S_group - zn_i . zn_i).  Zero exp accumulators.
// ---------------------------------------------------------------------------
#define PREP_SMEM ((32 * DIM + DIM) * 4)   // 67584 B

__global__ void __launch_bounds__(256) prep_kernel(const float* __restrict__ z) {
    extern __shared__ float sm[];
    float* sZ = sm;                 // [32][DIM]
    float* S  = sm + 32 * DIM;      // [DIM]
    const int grp = blockIdx.x, tid = threadIdx.x;
    const int wid = tid >> 5, lane = tid & 31;

    // Normalize: warp w handles rows 4w..4w+3
    #pragma unroll
    for (int rr = wid * 4; rr < wid * 4 + 4; ++rr) {
        const int row = grp * TSPAN + (rr & 15) + (rr >> 4) * (M_TOT / 2);
        const float4* src = (const float4*)(z + (size_t)row * DIM);
        float4 v[4]; float ss = 0.f;
        #pragma unroll
        for (int k = 0; k < 4; ++k) {
            v[k] = src[lane + k * 32];
            ss += v[k].x*v[k].x + v[k].y*v[k].y + v[k].z*v[k].z + v[k].w*v[k].w;
        }
        #pragma unroll
        for (int o = 16; o; o >>= 1) ss += __shfl_xor_sync(0xffffffffu, ss, o);
        const float rn = 1.0f / fmaxf(sqrtf(ss), 1e-8f);
        __nv_bfloat162* dst = (__nv_bfloat162*)(g_znb + (size_t)row * DIM);
        #pragma unroll
        for (int k = 0; k < 4; ++k) {
            const int idx = lane + k * 32;
            const float x0 = v[k].x*rn, x1 = v[k].y*rn, x2 = v[k].z*rn, x3 = v[k].w*rn;
            float* d = sZ + rr * DIM + idx * 4;
            d[0] = x0; d[1] = x1; d[2] = x2; d[3] = x3;
            dst[idx*2 + 0] = __floats2bfloat162_rn(x0, x1);
            dst[idx*2 + 1] = __floats2bfloat162_rn(x2, x3);
        }
    }
    __syncthreads();

    // Group sum S[d] (each thread 2 dims); zero exp accumulators
    {
        float s0 = 0.f, s1 = 0.f;
        #pragma unroll
        for (int r = 0; r < 32; ++r) {
            s0 += sZ[r * DIM + tid * 2];
            s1 += sZ[r * DIM + tid * 2 + 1];
        }
        S[tid * 2] = s0; S[tid * 2 + 1] = s1;
    }
    if (tid < 32) {
        const int row = grp * TSPAN + (tid & 15) + (tid >> 4) * (M_TOT / 2);
        g_rowExp[row] = 0.f;
    }
    __syncthreads();

    // Numerator per row (exact fp32)
    #pragma unroll
    for (int rr = wid * 4; rr < wid * 4 + 4; ++rr) {
        const int row = grp * TSPAN + (rr & 15) + (rr >> 4) * (M_TOT / 2);
        float d1 = 0.f, d2 = 0.f;
        const float4* zr = (const float4*)(sZ + rr * DIM);
        const float4* sr = (const float4*)S;
        #pragma unroll
        for (int j = 0; j < 4; ++j) {
            const float4 a = zr[lane + j * 32];
            const float4 b = sr[lane + j * 32];
            d1 += a.x*b.x + a.y*b.y + a.z*b.z + a.w*b.w;
            d2 += a.x*a.x + a.y*a.y + a.z*a.z + a.w*a.w;
        }
        #pragma unroll
        for (int o = 16; o; o >>= 1) {
            d1 += __shfl_xor_sync(0xffffffffu, d1, o);
            d2 += __shfl_xor_sync(0xffffffffu, d2, o);
        }
        if (lane == 0) g_rowNum[row] = 10.0f * (d1 - d2);
    }
}

// ---------------------------------------------------------------------------
// Kernel 2: bf16 symmetric fused GEMM + exp-sum (NO fused finalize).
// 528 upper-triangular 128x128 tiles. 3-stage cp.async pipeline, K-chunks
// of 64, proven loop (prefetch -> commit -> wait2 -> sync -> compute -> sync).
// ---------------------------------------------------------------------------
#define BT 128
#define KC 64
#define NCHUNK (DIM / KC)                  // 8
#define STAGE_BYTES 32768                  // A 16KB + B 16KB per stage
#define SMEM_BYTES  (3 * STAGE_BYTES)      // 98304

__global__ void __launch_bounds__(256, 2) gemm_kernel() {
    extern __shared__ __align__(16) unsigned char smem[];
    __shared__ float sRow[BT], sCol[BT];

    // Decode upper-triangular tile index: f(b) = b*(65-b)/2
    int idx = blockIdx.x;
    int bi = (int)(32.5f - sqrtf(1056.25f - 2.0f * (float)idx));
    if (bi < 0) bi = 0; if (bi > 31) bi = 31;
    while (bi * (65 - bi) / 2 > idx) --bi;
    while ((bi + 1) * (64 - bi) / 2 <= idx) ++bi;
    const int bj = bi + (idx - bi * (65 - bi) / 2);
    const bool diag = (bi == bj);
    const int rowBase = bi * BT, colBase = bj * BT;

    const int tid = threadIdx.x, lane = tid & 31, wid = tid >> 5;
    const int warp_m = wid & 1;        // 2 x 64 rows
    const int warp_n = wid >> 1;       // 4 x 32 cols
    const uint32_t sbase = smem_u32(smem);

    // Loader: 2 threads per row, 4 x 16B units each; swizzled 128B rows
    const int lr = tid >> 1;
    const int lu = (tid & 1) * 4;
    const __nv_bfloat16* gA = g_znb + (size_t)(rowBase + lr) * DIM + lu * 8;
    const __nv_bfloat16* gB = g_znb + (size_t)(colBase + lr) * DIM + lu * 8;
    uint32_t dstU[4];
    #pragma unroll
    for (int u = 0; u < 4; ++u)
        dstU[u] = sbase + lr * 128 + (((lu + u) ^ (lr & 7)) << 4);

    float acc[4][4][4];
    #pragma unroll
    for (int a = 0; a < 4; ++a)
        #pragma unroll
        for (int b = 0; b < 4; ++b)
            #pragma unroll
            for (int i = 0; i < 4; ++i) acc[a][b][i] = 0.f;

    // Prologue: stage chunks 0, 1
    #pragma unroll
    for (int s = 0; s < 2; ++s) {
        const uint32_t so = s * STAGE_BYTES;
        #pragma unroll
        for (int u = 0; u < 4; ++u) CP_ASYNC16(dstU[u] + so,         gA + s * KC + u * 8);
        #pragma unroll
        for (int u = 0; u < 4; ++u) CP_ASYNC16(dstU[u] + so + 16384, gB + s * KC + u * 8);
        CP_COMMIT();
    }

    // Main loop: prefetch first, commit every iter, wait_group 2.
    for (int ch = 0; ch < NCHUNK; ++ch) {
        if (ch + 2 < NCHUNK) {
            const uint32_t so = ((ch + 2) % 3) * STAGE_BYTES;
            #pragma unroll
            for (int u = 0; u < 4; ++u) CP_ASYNC16(dstU[u] + so,         gA + (ch + 2) * KC + u * 8);
            #pragma unroll
            for (int u = 0; u < 4; ++u) CP_ASYNC16(dstU[u] + so + 16384, gB + (ch + 2) * KC + u * 8);
        }
        CP_COMMIT();            // every iter -> uniform wait bound
        CP_WAIT2();             // chunk ch resident
        __syncthreads();

        const uint32_t Ab = sbase + (ch % 3) * STAGE_BYTES;
        const uint32_t Bb = Ab + 16384;
        #pragma unroll
        for (int ks = 0; ks < 4; ++ks) {
            uint32_t afr[4][4], bfr[2][4];
            #pragma unroll
            for (int mt = 0; mt < 4; ++mt) {
                const int m = warp_m * 64 + mt * 16 + (lane & 15);
                const int u = ks * 2 + (lane >> 4);
                ldsm4(Ab + m * 128 + ((u ^ (m & 7)) << 4), afr[mt]);
            }
            #pragma unroll
            for (int np = 0; np < 2; ++np) {
                const int n = warp_n * 32 + np * 16 + ((lane >> 4) << 3) + (lane & 7);
                const int u = ks * 2 + ((lane >> 3) & 1);
                ldsm4(Bb + n * 128 + ((u ^ (n & 7)) << 4), bfr[np]);
            }
            #pragma unroll
            for (int mt = 0; mt < 4; ++mt)
                #pragma unroll
                for (int np = 0; np < 2; ++np) {
                    mma16816(acc[mt][np * 2 + 0], afr[mt], bfr[np][0], bfr[np][1]);
                    mma16816(acc[mt][np * 2 + 1], afr[mt], bfr[np][2], bfr[np][3]);
                }
        }
        __syncthreads();        // protect stage about to be overwritten
    }

    // ---- Epilogue: exp + row sums (and col sums for off-diagonal tiles) ----
    const int gq = lane >> 2, tq = lane & 3;
    float accRow[4][2], accCol[4][2];
    #pragma unroll
    for (int a = 0; a < 4; ++a) { accRow[a][0]=accRow[a][1]=0.f; accCol[a][0]=accCol[a][1]=0.f; }

    #pragma unroll
    for (int mt = 0; mt < 4; ++mt)
        #pragma unroll
        for (int nn = 0; nn < 4; ++nn)
            #pragma unroll
            for (int i = 0; i < 4; ++i) {
                float e = exp10x(acc[mt][nn][i]);
                if (diag) {
                    const int dR = warp_m * 64 + mt * 16 + gq + (i >> 1) * 8;
                    const int dC = warp_n * 32 + nn * 8 + tq * 2 + (i & 1);
                    if (dR == dC) e = 0.f;
                }
                accRow[mt][i >> 1] += e;
                accCol[nn][i & 1]  += e;
            }

    #pragma unroll
    for (int o = 1; o <= 2; o <<= 1)
        #pragma unroll
        for (int mt = 0; mt < 4; ++mt) {
            accRow[mt][0] += __shfl_xor_sync(0xffffffffu, accRow[mt][0], o);
            accRow[mt][1] += __shfl_xor_sync(0xffffffffu, accRow[mt][1], o);
        }
    if (!diag) {
        #pragma unroll
        for (int o = 4; o <= 16; o <<= 1)
            #pragma unroll
            for (int nn = 0; nn < 4; ++nn) {
                accCol[nn][0] += __shfl_xor_sync(0xffffffffu, accCol[nn][0], o);
                accCol[nn][1] += __shfl_xor_sync(0xffffffffu, accCol[nn][1], o);
            }
    }

    __syncthreads();
    if (tid < BT) { sRow[tid] = 0.f; sCol[tid] = 0.f; }
    __syncthreads();
    if (tq == 0) {
        #pragma unroll
        for (int mt = 0; mt < 4; ++mt)
            #pragma unroll
            for (int ih = 0; ih < 2; ++ih)
                atomicAdd(&sRow[warp_m * 64 + mt * 16 + gq + ih * 8], accRow[mt][ih]);
    }
    if (!diag && gq == 0) {
        #pragma unroll
        for (int nn = 0; nn < 4; ++nn)
            #pragma unroll
            for (int j = 0; j < 2; ++j)
                atomicAdd(&sCol[warp_n * 32 + nn * 8 + tq * 2 + j], accCol[nn][j]);
    }
    __syncthreads();
    if (tid < BT) {
        atomicAdd(&g_rowExp[rowBase + tid], sRow[tid]);
        if (!diag) atomicAdd(&g_rowExp[colBase + tid], sCol[tid]);
    }
}

// ---------------------------------------------------------------------------
// Kernel 3: per-row loss + global mean (separate launch; cheap)
// ---------------------------------------------------------------------------
__global__ void finalize_kernel(float* __restrict__ out) {
    int tid = threadIdx.x;   // 1024 threads
    float s = 0.f;
    #pragma unroll
    for (int k = 0; k < 4; ++k) {
        int r = tid + k * 1024;
        s += g_rowNum[r] * NEG_INV - __logf(g_rowExp[r]);
    }
    #pragma unroll
    for (int o = 16; o; o >>= 1) s += __shfl_xor_sync(0xffffffffu, s, o);
    __shared__ float ws[32];
    if ((tid & 31) == 0) ws[tid >> 5] = s;
    __syncthreads();
    if (tid < 32) {
        float v = ws[tid];
        #pragma unroll
        for (int o = 16; o; o >>= 1) v += __shfl_xor_sync(0xffffffffu, v, o);
        if (tid == 0) out[0] = -v / (float)M_TOT;
    }
}

// ---------------------------------------------------------------------------
extern "C" void kernel_launch(void* const* d_in, const int* in_sizes, int n_in,
                              void* d_out, int out_size) {
    const float* z = (const float*)d_in[0];
    if (n_in > 1 && in_sizes[0] != M_TOT * DIM) z = (const float*)d_in[1];

    cudaFuncSetAttribute(prep_kernel, cudaFuncAttributeMaxDynamicSharedMemorySize, PREP_SMEM);
    cudaFuncSetAttribute(gemm_kernel, cudaFuncAttributeMaxDynamicSharedMemorySize, SMEM_BYTES);

    prep_kernel<<<128, 256, PREP_SMEM>>>(z);
    gemm_kernel<<<528, 256, SMEM_BYTES>>>();
    finalize_kernel<<<1, 1024>>>((float*)d_out);
}

// round 13
// speedup vs baseline: 1.2487x; 1.0065x over previous
#include <cuda_runtime.h>
#include <cuda_bf16.h>
#include <cstdint>
#include <math.h>

// Problem constants
#define M_TOT 4096      // 2*N*T
#define DIM   512
#define TSPAN 16
#define NEG_INV (1.0f/31.0f)

// Device scratch (no allocs allowed)
__device__ __nv_bfloat16 g_znb[M_TOT * DIM];   // normalized z, bf16 (4 MB)
__device__ float g_rowExp[M_TOT];
__device__ float g_rowNum[M_TOT];

// ---------------------------------------------------------------------------
// helpers
// ---------------------------------------------------------------------------
__device__ __forceinline__ uint32_t smem_u32(const void* p) {
    return (uint32_t)__cvta_generic_to_shared(p);
}
__device__ __forceinline__ void ldsm4(uint32_t addr, uint32_t* r) {
    asm volatile("ldmatrix.sync.aligned.m8n8.x4.shared.b16 {%0,%1,%2,%3}, [%4];"
                 : "=r"(r[0]), "=r"(r[1]), "=r"(r[2]), "=r"(r[3]) : "r"(addr));
}
__device__ __forceinline__ void mma16816(float* c, const uint32_t* a, uint32_t b0, uint32_t b1) {
    asm volatile("mma.sync.aligned.m16n8k16.row.col.f32.bf16.bf16.f32 "
                 "{%0,%1,%2,%3}, {%4,%5,%6,%7}, {%8,%9}, {%0,%1,%2,%3};"
                 : "+f"(c[0]), "+f"(c[1]), "+f"(c[2]), "+f"(c[3])
                 : "r"(a[0]), "r"(a[1]), "r"(a[2]), "r"(a[3]), "r"(b0), "r"(b1));
}
#define CP_ASYNC16(dst, src) \
    asm volatile("cp.async.cg.shared.global [%0], [%1], 16;\n" :: "r"(dst), "l"(src))
#define CP_COMMIT() asm volatile("cp.async.commit_group;\n" ::: "memory")
#define CP_WAIT2()  asm volatile("cp.async.wait_group 2;\n" ::: "memory")

// FFMA-only exp(10*a): 2^(a*14.4269504), degree-5 poly on [-0.5, 0.5]
__device__ __forceinline__ float exp10x(float a) {
    const float L = 14.4269504f;
    const float tk = __fmaf_rn(a, L, 12582912.0f);
    const int   X  = __float_as_int(tk);
    const float kf = tk - 12582912.0f;
    const float f  = __fmaf_rn(a, L, -kf);
    float p = 1.3333558e-3f;
    p = __fmaf_rn(p, f, 9.6181291e-3f);
    p = __fmaf_rn(p, f, 5.5504109e-2f);
    p = __fmaf_rn(p, f, 2.4022651e-1f);
    p = __fmaf_rn(p, f, 6.9314718e-1f);
    p = __fmaf_rn(p, f, 1.0f);
    return p * __int_as_float((X << 23) + 0x3F800000);
}

// ---------------------------------------------------------------------------
// Kernel 1 (fused prep + groupnum), 1024 threads: warp w <-> group row w.
// Normalize fp32 -> write bf16, group sums in fp32 from smem, exact numerator
//   num_i = 10 * (zn_i . S_group - zn_i . zn_i).  Zero exp accumulators.
// ---------------------------------------------------------------------------
#define PREP_SMEM ((32 * DIM + 2 * DIM) * 4)   // 64KB + 4KB

__global__ void __launch_bounds__(1024) prep_kernel(const float* __restrict__ z) {
    extern __shared__ float sm[];
    float* sZ = sm;                  // [32][DIM]
    float* SP = sm + 32 * DIM;       // [2][DIM] partial group sums
    const int grp = blockIdx.x, tid = threadIdx.x;
    const int wid = tid >> 5, lane = tid & 31;

    // Warp w normalizes row w of the group (16 from view 0, 16 from view 1)
    const int row = grp * TSPAN + (wid & 15) + (wid >> 4) * (M_TOT / 2);
    {
        const float4* src = (const float4*)(z + (size_t)row * DIM);
        float4 v[4]; float ss = 0.f;
        #pragma unroll
        for (int k = 0; k < 4; ++k) {
            v[k] = src[lane + k * 32];
            ss += v[k].x*v[k].x + v[k].y*v[k].y + v[k].z*v[k].z + v[k].w*v[k].w;
        }
        #pragma unroll
        for (int o = 16; o; o >>= 1) ss += __shfl_xor_sync(0xffffffffu, ss, o);
        const float rn = 1.0f / fmaxf(sqrtf(ss), 1e-8f);
        __nv_bfloat162* dst = (__nv_bfloat162*)(g_znb + (size_t)row * DIM);
        float4* srow = (float4*)(sZ + wid * DIM);
        #pragma unroll
        for (int k = 0; k < 4; ++k) {
            const int idx = lane + k * 32;
            float4 x;
            x.x = v[k].x*rn; x.y = v[k].y*rn; x.z = v[k].z*rn; x.w = v[k].w*rn;
            srow[idx] = x;
            dst[idx*2 + 0] = __floats2bfloat162_rn(x.x, x.y);
            dst[idx*2 + 1] = __floats2bfloat162_rn(x.z, x.w);
        }
    }
    if (lane == 0) g_rowExp[row] = 0.f;
    __syncthreads();

    // Partial group sums: thread handles dim (tid&511), half (tid>>9)
    {
        const int d = tid & (DIM - 1);
        const int half = tid >> 9;           // 0 or 1
        float s = 0.f;
        #pragma unroll
        for (int r = 0; r < 16; ++r) s += sZ[(half * 16 + r) * DIM + d];
        SP[half * DIM + d] = s;
    }
    __syncthreads();

    // Numerator: warp w computes row w's dot with the group sum
    {
        float d1 = 0.f, d2 = 0.f;
        const float4* zr  = (const float4*)(sZ + wid * DIM);
        const float4* s0  = (const float4*)SP;
        const float4* s1  = (const float4*)(SP + DIM);
        #pragma unroll
        for (int j = 0; j < 4; ++j) {
            const float4 a  = zr[lane + j * 32];
            const float4 p0 = s0[lane + j * 32];
            const float4 p1 = s1[lane + j * 32];
            d1 += a.x*(p0.x+p1.x) + a.y*(p0.y+p1.y) + a.z*(p0.z+p1.z) + a.w*(p0.w+p1.w);
            d2 += a.x*a.x + a.y*a.y + a.z*a.z + a.w*a.w;
        }
        #pragma unroll
        for (int o = 16; o; o >>= 1) {
            d1 += __shfl_xor_sync(0xffffffffu, d1, o);
            d2 += __shfl_xor_sync(0xffffffffu, d2, o);
        }
        if (lane == 0) g_rowNum[row] = 10.0f * (d1 - d2);
    }
}

// ---------------------------------------------------------------------------
// Kernel 2: bf16 symmetric fused GEMM + exp-sum (proven R12 structure).
// 528 upper-triangular 128x128 tiles. 3-stage cp.async pipeline, K-chunks
// of 64 (prefetch -> commit -> wait2 -> sync -> compute -> sync).
// ---------------------------------------------------------------------------
#define BT 128
#define KC 64
#define NCHUNK (DIM / KC)                  // 8
#define STAGE_BYTES 32768                  // A 16KB + B 16KB per stage
#define SMEM_BYTES  (3 * STAGE_BYTES)      // 98304

__global__ void __launch_bounds__(256, 2) gemm_kernel() {
    extern __shared__ __align__(16) unsigned char smem[];
    __shared__ float sRow[BT], sCol[BT];

    // Decode upper-triangular tile index: f(b) = b*(65-b)/2
    int idx = blockIdx.x;
    int bi = (int)(32.5f - sqrtf(1056.25f - 2.0f * (float)idx));
    if (bi < 0) bi = 0; if (bi > 31) bi = 31;
    while (bi * (65 - bi) / 2 > idx) --bi;
    while ((bi + 1) * (64 - bi) / 2 <= idx) ++bi;
    const int bj = bi + (idx - bi * (65 - bi) / 2);
    const bool diag = (bi == bj);
    const int rowBase = bi * BT, colBase = bj * BT;

    const int tid = threadIdx.x, lane = tid & 31, wid = tid >> 5;
    const int warp_m = wid & 1;        // 2 x 64 rows
    const int warp_n = wid >> 1;       // 4 x 32 cols
    const uint32_t sbase = smem_u32(smem);

    // Zero the reduction buffers up front (no one touches them until epilogue)
    if (tid < BT) { sRow[tid] = 0.f; sCol[tid] = 0.f; }

    // Loader: 2 threads per row, 4 x 16B units each; swizzled 128B rows
    const int lr = tid >> 1;
    const int lu = (tid & 1) * 4;
    const __nv_bfloat16* gA = g_znb + (size_t)(rowBase + lr) * DIM + lu * 8;
    const __nv_bfloat16* gB = g_znb + (size_t)(colBase + lr) * DIM + lu * 8;
    uint32_t dstU[4];
    #pragma unroll
    for (int u = 0; u < 4; ++u)
        dstU[u] = sbase + lr * 128 + (((lu + u) ^ (lr & 7)) << 4);

    float acc[4][4][4];
    #pragma unroll
    for (int a = 0; a < 4; ++a)
        #pragma unroll
        for (int b = 0; b < 4; ++b)
            #pragma unroll
            for (int i = 0; i < 4; ++i) acc[a][b][i] = 0.f;

    // Prologue: stage chunks 0, 1
    #pragma unroll
    for (int s = 0; s < 2; ++s) {
        const uint32_t so = s * STAGE_BYTES;
        #pragma unroll
        for (int u = 0; u < 4; ++u) CP_ASYNC16(dstU[u] + so,         gA + s * KC + u * 8);
        #pragma unroll
        for (int u = 0; u < 4; ++u) CP_ASYNC16(dstU[u] + so + 16384, gB + s * KC + u * 8);
        CP_COMMIT();
    }

    // Main loop: prefetch first, commit every iter, wait_group 2.
    for (int ch = 0; ch < NCHUNK; ++ch) {
        if (ch + 2 < NCHUNK) {
            const uint32_t so = ((ch + 2) % 3) * STAGE_BYTES;
            #pragma unroll
            for (int u = 0; u < 4; ++u) CP_ASYNC16(dstU[u] + so,         gA + (ch + 2) * KC + u * 8);
            #pragma unroll
            for (int u = 0; u < 4; ++u) CP_ASYNC16(dstU[u] + so + 16384, gB + (ch + 2) * KC + u * 8);
        }
        CP_COMMIT();            // every iter -> uniform wait bound
        CP_WAIT2();             // chunk ch resident
        __syncthreads();

        const uint32_t Ab = sbase + (ch % 3) * STAGE_BYTES;
        const uint32_t Bb = Ab + 16384;
        #pragma unroll
        for (int ks = 0; ks < 4; ++ks) {
            uint32_t afr[4][4], bfr[2][4];
            #pragma unroll
            for (int mt = 0; mt < 4; ++mt) {
                const int m = warp_m * 64 + mt * 16 + (lane & 15);
                const int u = ks * 2 + (lane >> 4);
                ldsm4(Ab + m * 128 + ((u ^ (m & 7)) << 4), afr[mt]);
            }
            #pragma unroll
            for (int np = 0; np < 2; ++np) {
                const int n = warp_n * 32 + np * 16 + ((lane >> 4) << 3) + (lane & 7);
                const int u = ks * 2 + ((lane >> 3) & 1);
                ldsm4(Bb + n * 128 + ((u ^ (n & 7)) << 4), bfr[np]);
            }
            #pragma unroll
            for (int mt = 0; mt < 4; ++mt)
                #pragma unroll
                for (int np = 0; np < 2; ++np) {
                    mma16816(acc[mt][np * 2 + 0], afr[mt], bfr[np][0], bfr[np][1]);
                    mma16816(acc[mt][np * 2 + 1], afr[mt], bfr[np][2], bfr[np][3]);
                }
        }
        __syncthreads();        // protect stage about to be overwritten
    }

    // ---- Epilogue: exp + row sums (and col sums for off-diagonal tiles) ----
    const int gq = lane >> 2, tq = lane & 3;
    float accRow[4][2], accCol[4][2];
    #pragma unroll
    for (int a = 0; a < 4; ++a) { accRow[a][0]=accRow[a][1]=0.f; accCol[a][0]=accCol[a][1]=0.f; }

    #pragma unroll
    for (int mt = 0; mt < 4; ++mt)
        #pragma unroll
        for (int nn = 0; nn < 4; ++nn)
            #pragma unroll
            for (int i = 0; i < 4; ++i) {
                float e = exp10x(acc[mt][nn][i]);
                if (diag) {
                    const int dR = warp_m * 64 + mt * 16 + gq + (i >> 1) * 8;
                    const int dC = warp_n * 32 + nn * 8 + tq * 2 + (i & 1);
                    if (dR == dC) e = 0.f;
                }
                accRow[mt][i >> 1] += e;
                accCol[nn][i & 1]  += e;
            }

    #pragma unroll
    for (int o = 1; o <= 2; o <<= 1)
        #pragma unroll
        for (int mt = 0; mt < 4; ++mt) {
            accRow[mt][0] += __shfl_xor_sync(0xffffffffu, accRow[mt][0], o);
            accRow[mt][1] += __shfl_xor_sync(0xffffffffu, accRow[mt][1], o);
        }
    if (!diag) {
        #pragma unroll
        for (int o = 4; o <= 16; o <<= 1)
            #pragma unroll
            for (int nn = 0; nn < 4; ++nn) {
                accCol[nn][0] += __shfl_xor_sync(0xffffffffu, accCol[nn][0], o);
                accCol[nn][1] += __shfl_xor_sync(0xffffffffu, accCol[nn][1], o);
            }
    }

    // sRow/sCol were zeroed at kernel entry; last mainloop sync ordered it.
    if (tq == 0) {
        #pragma unroll
        for (int mt = 0; mt < 4; ++mt)
            #pragma unroll
            for (int ih = 0; ih < 2; ++ih)
                atomicAdd(&sRow[warp_m * 64 + mt * 16 + gq + ih * 8], accRow[mt][ih]);
    }
    if (!diag && gq == 0) {
        #pragma unroll
        for (int nn = 0; nn < 4; ++nn)
            #pragma unroll
            for (int j = 0; j < 2; ++j)
                atomicAdd(&sCol[warp_n * 32 + nn * 8 + tq * 2 + j], accCol[nn][j]);
    }
    __syncthreads();
    if (tid < BT) {
        atomicAdd(&g_rowExp[rowBase + tid], sRow[tid]);
        if (!diag) atomicAdd(&g_rowExp[colBase + tid], sCol[tid]);
    }
}

// ---------------------------------------------------------------------------
// Kernel 3: per-row loss + global mean (separate launch; cheap)
// ---------------------------------------------------------------------------
__global__ void finalize_kernel(float* __restrict__ out) {
    int tid = threadIdx.x;   // 1024 threads
    float s = 0.f;
    #pragma unroll
    for (int k = 0; k < 4; ++k) {
        int r = tid + k * 1024;
        s += g_rowNum[r] * NEG_INV - __logf(g_rowExp[r]);
    }
    #pragma unroll
    for (int o = 16; o; o >>= 1) s += __shfl_xor_sync(0xffffffffu, s, o);
    __shared__ float ws[32];
    if ((tid & 31) == 0) ws[tid >> 5] = s;
    __syncthreads();
    if (tid < 32) {
        float v = ws[tid];
        #pragma unroll
        for (int o = 16; o; o >>= 1) v += __shfl_xor_sync(0xffffffffu, v, o);
        if (tid == 0) out[0] = -v / (float)M_TOT;
    }
}

// ---------------------------------------------------------------------------
extern "C" void kernel_launch(void* const* d_in, const int* in_sizes, int n_in,
                              void* d_out, int out_size) {
    const float* z = (const float*)d_in[0];
    if (n_in > 1 && in_sizes[0] != M_TOT * DIM) z = (const float*)d_in[1];

    cudaFuncSetAttribute(prep_kernel, cudaFuncAttributeMaxDynamicSharedMemorySize, PREP_SMEM);
    cudaFuncSetAttribute(gemm_kernel, cudaFuncAttributeMaxDynamicSharedMemorySize, SMEM_BYTES);

    prep_kernel<<<128, 1024, PREP_SMEM>>>(z);
    gemm_kernel<<<528, 256, SMEM_BYTES>>>();
    finalize_kernel<<<1, 1024>>>((float*)d_out);
}

// round 14
// speedup vs baseline: 1.2863x; 1.0301x over previous
#include <cuda_runtime.h>
#include <cuda_bf16.h>
#include <cstdint>
#include <math.h>

// Problem constants
#define M_TOT 4096      // 2*N*T
#define DIM   512
#define TSPAN 16
#define NEG_INV (1.0f/31.0f)

// Device scratch (no allocs allowed)
__device__ __nv_bfloat16 g_znb[M_TOT * DIM];   // normalized z, bf16 (4 MB)
__device__ float g_rowExp[M_TOT];
__device__ float g_rowNum[M_TOT];

// ---------------------------------------------------------------------------
// helpers
// ---------------------------------------------------------------------------
__device__ __forceinline__ uint32_t smem_u32(const void* p) {
    return (uint32_t)__cvta_generic_to_shared(p);
}
__device__ __forceinline__ void ldsm4(uint32_t addr, uint32_t* r) {
    asm volatile("ldmatrix.sync.aligned.m8n8.x4.shared.b16 {%0,%1,%2,%3}, [%4];"
                 : "=r"(r[0]), "=r"(r[1]), "=r"(r[2]), "=r"(r[3]) : "r"(addr));
}
__device__ __forceinline__ void mma16816(float* c, const uint32_t* a, uint32_t b0, uint32_t b1) {
    asm volatile("mma.sync.aligned.m16n8k16.row.col.f32.bf16.bf16.f32 "
                 "{%0,%1,%2,%3}, {%4,%5,%6,%7}, {%8,%9}, {%0,%1,%2,%3};"
                 : "+f"(c[0]), "+f"(c[1]), "+f"(c[2]), "+f"(c[3])
                 : "r"(a[0]), "r"(a[1]), "r"(a[2]), "r"(a[3]), "r"(b0), "r"(b1));
}
#define CP_ASYNC16(dst, src) \
    asm volatile("cp.async.cg.shared.global [%0], [%1], 16;\n" :: "r"(dst), "l"(src))
#define CP_COMMIT() asm volatile("cp.async.commit_group;\n" ::: "memory")
#define CP_WAIT2()  asm volatile("cp.async.wait_group 2;\n" ::: "memory")

// FFMA-only exp(10*a): 2^(a*14.4269504), degree-5 poly on [-0.5, 0.5]
__device__ __forceinline__ float exp10x(float a) {
    const float L = 14.4269504f;
    const float tk = __fmaf_rn(a, L, 12582912.0f);
    const int   X  = __float_as_int(tk);
    const float kf = tk - 12582912.0f;
    const float f  = __fmaf_rn(a, L, -kf);
    float p = 1.3333558e-3f;
    p = __fmaf_rn(p, f, 9.6181291e-3f);
    p = __fmaf_rn(p, f, 5.5504109e-2f);
    p = __fmaf_rn(p, f, 2.4022651e-1f);
    p = __fmaf_rn(p, f, 6.9314718e-1f);
    p = __fmaf_rn(p, f, 1.0f);
    return p * __int_as_float((X << 23) + 0x3F800000);
}

// ---------------------------------------------------------------------------
// Kernel 1 (fused prep + groupnum), 1024 threads: warp w <-> group row w.
// (unchanged from R13)
// ---------------------------------------------------------------------------
#define PREP_SMEM ((32 * DIM + 2 * DIM) * 4)   // 64KB + 4KB

__global__ void __launch_bounds__(1024) prep_kernel(const float* __restrict__ z) {
    extern __shared__ float sm[];
    float* sZ = sm;                  // [32][DIM]
    float* SP = sm + 32 * DIM;       // [2][DIM] partial group sums
    const int grp = blockIdx.x, tid = threadIdx.x;
    const int wid = tid >> 5, lane = tid & 31;

    const int row = grp * TSPAN + (wid & 15) + (wid >> 4) * (M_TOT / 2);
    {
        const float4* src = (const float4*)(z + (size_t)row * DIM);
        float4 v[4]; float ss = 0.f;
        #pragma unroll
        for (int k = 0; k < 4; ++k) {
            v[k] = src[lane + k * 32];
            ss += v[k].x*v[k].x + v[k].y*v[k].y + v[k].z*v[k].z + v[k].w*v[k].w;
        }
        #pragma unroll
        for (int o = 16; o; o >>= 1) ss += __shfl_xor_sync(0xffffffffu, ss, o);
        const float rn = 1.0f / fmaxf(sqrtf(ss), 1e-8f);
        __nv_bfloat162* dst = (__nv_bfloat162*)(g_znb + (size_t)row * DIM);
        float4* srow = (float4*)(sZ + wid * DIM);
        #pragma unroll
        for (int k = 0; k < 4; ++k) {
            const int idx = lane + k * 32;
            float4 x;
            x.x = v[k].x*rn; x.y = v[k].y*rn; x.z = v[k].z*rn; x.w = v[k].w*rn;
            srow[idx] = x;
            dst[idx*2 + 0] = __floats2bfloat162_rn(x.x, x.y);
            dst[idx*2 + 1] = __floats2bfloat162_rn(x.z, x.w);
        }
    }
    if (lane == 0) g_rowExp[row] = 0.f;
    __syncthreads();

    {
        const int d = tid & (DIM - 1);
        const int half = tid >> 9;           // 0 or 1
        float s = 0.f;
        #pragma unroll
        for (int r = 0; r < 16; ++r) s += sZ[(half * 16 + r) * DIM + d];
        SP[half * DIM + d] = s;
    }
    __syncthreads();

    {
        float d1 = 0.f, d2 = 0.f;
        const float4* zr  = (const float4*)(sZ + wid * DIM);
        const float4* s0  = (const float4*)SP;
        const float4* s1  = (const float4*)(SP + DIM);
        #pragma unroll
        for (int j = 0; j < 4; ++j) {
            const float4 a  = zr[lane + j * 32];
            const float4 p0 = s0[lane + j * 32];
            const float4 p1 = s1[lane + j * 32];
            d1 += a.x*(p0.x+p1.x) + a.y*(p0.y+p1.y) + a.z*(p0.z+p1.z) + a.w*(p0.w+p1.w);
            d2 += a.x*a.x + a.y*a.y + a.z*a.z + a.w*a.w;
        }
        #pragma unroll
        for (int o = 16; o; o >>= 1) {
            d1 += __shfl_xor_sync(0xffffffffu, d1, o);
            d2 += __shfl_xor_sync(0xffffffffu, d2, o);
        }
        if (lane == 0) g_rowNum[row] = 10.0f * (d1 - d2);
    }
}

// ---------------------------------------------------------------------------
// Kernel 2: bf16 symmetric fused GEMM + exp-sum.
// R12/R13 structure + fragment double-buffering across the ks loop.
// ---------------------------------------------------------------------------
#define BT 128
#define KC 64
#define NCHUNK (DIM / KC)                  // 8
#define STAGE_BYTES 32768                  // A 16KB + B 16KB per stage
#define SMEM_BYTES  (3 * STAGE_BYTES)      // 98304

__global__ void __launch_bounds__(256, 2) gemm_kernel() {
    extern __shared__ __align__(16) unsigned char smem[];
    __shared__ float sRow[BT], sCol[BT];

    // Decode upper-triangular tile index: f(b) = b*(65-b)/2
    int idx = blockIdx.x;
    int bi = (int)(32.5f - sqrtf(1056.25f - 2.0f * (float)idx));
    if (bi < 0) bi = 0; if (bi > 31) bi = 31;
    while (bi * (65 - bi) / 2 > idx) --bi;
    while ((bi + 1) * (64 - bi) / 2 <= idx) ++bi;
    const int bj = bi + (idx - bi * (65 - bi) / 2);
    const bool diag = (bi == bj);
    const int rowBase = bi * BT, colBase = bj * BT;

    const int tid = threadIdx.x, lane = tid & 31, wid = tid >> 5;
    const int warp_m = wid & 1;        // 2 x 64 rows
    const int warp_n = wid >> 1;       // 4 x 32 cols
    const uint32_t sbase = smem_u32(smem);

    if (tid < BT) { sRow[tid] = 0.f; sCol[tid] = 0.f; }

    // Loader: 2 threads per row, 4 x 16B units each; swizzled 128B rows
    const int lr = tid >> 1;
    const int lu = (tid & 1) * 4;
    const __nv_bfloat16* gA = g_znb + (size_t)(rowBase + lr) * DIM + lu * 8;
    const __nv_bfloat16* gB = g_znb + (size_t)(colBase + lr) * DIM + lu * 8;
    uint32_t dstU[4];
    #pragma unroll
    for (int u = 0; u < 4; ++u)
        dstU[u] = sbase + lr * 128 + (((lu + u) ^ (lr & 7)) << 4);

    // Per-warp ldsm lane-row bases (row part is ks-invariant)
    const int mrowA = warp_m * 64 + (lane & 15);           // + mt*16
    const int uA_half = lane >> 4;                          // ks*2 + this
    const int nrowB = warp_n * 32 + ((lane >> 4) << 3) + (lane & 7);  // + np*16
    const int uB_half = (lane >> 3) & 1;

    float acc[4][4][4];
    #pragma unroll
    for (int a = 0; a < 4; ++a)
        #pragma unroll
        for (int b = 0; b < 4; ++b)
            #pragma unroll
            for (int i = 0; i < 4; ++i) acc[a][b][i] = 0.f;

    // Prologue: stage chunks 0, 1
    #pragma unroll
    for (int s = 0; s < 2; ++s) {
        const uint32_t so = s * STAGE_BYTES;
        #pragma unroll
        for (int u = 0; u < 4; ++u) CP_ASYNC16(dstU[u] + so,         gA + s * KC + u * 8);
        #pragma unroll
        for (int u = 0; u < 4; ++u) CP_ASYNC16(dstU[u] + so + 16384, gB + s * KC + u * 8);
        CP_COMMIT();
    }

    uint32_t afr[2][4][4], bfr[2][2][4];

    // Main loop: prefetch first, commit every iter, wait_group 2.
    for (int ch = 0; ch < NCHUNK; ++ch) {
        if (ch + 2 < NCHUNK) {
            const uint32_t so = ((ch + 2) % 3) * STAGE_BYTES;
            #pragma unroll
            for (int u = 0; u < 4; ++u) CP_ASYNC16(dstU[u] + so,         gA + (ch + 2) * KC + u * 8);
            #pragma unroll
            for (int u = 0; u < 4; ++u) CP_ASYNC16(dstU[u] + so + 16384, gB + (ch + 2) * KC + u * 8);
        }
        CP_COMMIT();            // every iter -> uniform wait bound
        CP_WAIT2();             // chunk ch resident
        __syncthreads();

        const uint32_t Ab = sbase + (ch % 3) * STAGE_BYTES;
        const uint32_t Bb = Ab + 16384;

        // Load fragments for ks=0
        {
            const int u = uA_half;           // ks=0
            #pragma unroll
            for (int mt = 0; mt < 4; ++mt) {
                const int m = mrowA + mt * 16;
                ldsm4(Ab + m * 128 + ((u ^ (m & 7)) << 4), afr[0][mt]);
            }
            const int ub = uB_half;
            #pragma unroll
            for (int np = 0; np < 2; ++np) {
                const int n = nrowB + np * 16;
                ldsm4(Bb + n * 128 + ((ub ^ (n & 7)) << 4), bfr[0][np]);
            }
        }

        #pragma unroll
        for (int ks = 0; ks < 4; ++ks) {
            const int cur = ks & 1, nxt = cur ^ 1;
            if (ks < 3) {   // prefetch ks+1 fragments before consuming ks
                const int u = (ks + 1) * 2 + uA_half;
                #pragma unroll
                for (int mt = 0; mt < 4; ++mt) {
                    const int m = mrowA + mt * 16;
                    ldsm4(Ab + m * 128 + ((u ^ (m & 7)) << 4), afr[nxt][mt]);
                }
                const int ub = (ks + 1) * 2 + uB_half;
                #pragma unroll
                for (int np = 0; np < 2; ++np) {
                    const int n = nrowB + np * 16;
                    ldsm4(Bb + n * 128 + ((ub ^ (n & 7)) << 4), bfr[nxt][np]);
                }
            }
            #pragma unroll
            for (int mt = 0; mt < 4; ++mt)
                #pragma unroll
                for (int np = 0; np < 2; ++np) {
                    mma16816(acc[mt][np * 2 + 0], afr[cur][mt], bfr[cur][np][0], bfr[cur][np][1]);
                    mma16816(acc[mt][np * 2 + 1], afr[cur][mt], bfr[cur][np][2], bfr[cur][np][3]);
                }
        }
        __syncthreads();        // protect stage about to be overwritten
    }

    // ---- Epilogue: exp + row sums (and col sums for off-diagonal tiles) ----
    const int gq = lane >> 2, tq = lane & 3;
    float accRow[4][2], accCol[4][2];
    #pragma unroll
    for (int a = 0; a < 4; ++a) { accRow[a][0]=accRow[a][1]=0.f; accCol[a][0]=accCol[a][1]=0.f; }

    #pragma unroll
    for (int mt = 0; mt < 4; ++mt)
        #pragma unroll
        for (int nn = 0; nn < 4; ++nn)
            #pragma unroll
            for (int i = 0; i < 4; ++i) {
                float e = exp10x(acc[mt][nn][i]);
                if (diag) {
                    const int dR = warp_m * 64 + mt * 16 + gq + (i >> 1) * 8;
                    const int dC = warp_n * 32 + nn * 8 + tq * 2 + (i & 1);
                    if (dR == dC) e = 0.f;
                }
                accRow[mt][i >> 1] += e;
                accCol[nn][i & 1]  += e;
            }

    #pragma unroll
    for (int o = 1; o <= 2; o <<= 1)
        #pragma unroll
        for (int mt = 0; mt < 4; ++mt) {
            accRow[mt][0] += __shfl_xor_sync(0xffffffffu, accRow[mt][0], o);
            accRow[mt][1] += __shfl_xor_sync(0xffffffffu, accRow[mt][1], o);
        }
    if (!diag) {
        #pragma unroll
        for (int o = 4; o <= 16; o <<= 1)
            #pragma unroll
            for (int nn = 0; nn < 4; ++nn) {
                accCol[nn][0] += __shfl_xor_sync(0xffffffffu, accCol[nn][0], o);
                accCol[nn][1] += __shfl_xor_sync(0xffffffffu, accCol[nn][1], o);
            }
    }

    // sRow/sCol were zeroed at kernel entry; last mainloop sync ordered it.
    if (tq == 0) {
        #pragma unroll
        for (int mt = 0; mt < 4; ++mt)
            #pragma unroll
            for (int ih = 0; ih < 2; ++ih)
                atomicAdd(&sRow[warp_m * 64 + mt * 16 + gq + ih * 8], accRow[mt][ih]);
    }
    if (!diag && gq == 0) {
        #pragma unroll
        for (int nn = 0; nn < 4; ++nn)
            #pragma unroll
            for (int j = 0; j < 2; ++j)
                atomicAdd(&sCol[warp_n * 32 + nn * 8 + tq * 2 + j], accCol[nn][j]);
    }
    __syncthreads();
    if (tid < BT) {
        atomicAdd(&g_rowExp[rowBase + tid], sRow[tid]);
        if (!diag) atomicAdd(&g_rowExp[colBase + tid], sCol[tid]);
    }
}

// ---------------------------------------------------------------------------
// Kernel 3: per-row loss + global mean (separate launch; cheap)
// ---------------------------------------------------------------------------
__global__ void finalize_kernel(float* __restrict__ out) {
    int tid = threadIdx.x;   // 1024 threads
    float s = 0.f;
    #pragma unroll
    for (int k = 0; k < 4; ++k) {
        int r = tid + k * 1024;
        s += g_rowNum[r] * NEG_INV - __logf(g_rowExp[r]);
    }
    #pragma unroll
    for (int o = 16; o; o >>= 1) s += __shfl_xor_sync(0xffffffffu, s, o);
    __shared__ float ws[32];
    if ((tid & 31) == 0) ws[tid >> 5] = s;
    __syncthreads();
    if (tid < 32) {
        float v = ws[tid];
        #pragma unroll
        for (int o = 16; o; o >>= 1) v += __shfl_xor_sync(0xffffffffu, v, o);
        if (tid == 0) out[0] = -v / (float)M_TOT;
    }
}

// ---------------------------------------------------------------------------
extern "C" void kernel_launch(void* const* d_in, const int* in_sizes, int n_in,
                              void* d_out, int out_size) {
    const float* z = (const float*)d_in[0];
    if (n_in > 1 && in_sizes[0] != M_TOT * DIM) z = (const float*)d_in[1];

    cudaFuncSetAttribute(prep_kernel, cudaFuncAttributeMaxDynamicSharedMemorySize, PREP_SMEM);
    cudaFuncSetAttribute(gemm_kernel, cudaFuncAttributeMaxDynamicSharedMemorySize, SMEM_BYTES);

    prep_kernel<<<128, 1024, PREP_SMEM>>>(z);
    gemm_kernel<<<528, 256, SMEM_BYTES>>>();
    finalize_kernel<<<1, 1024>>>((float*)d_out);
}

// round 15
// speedup vs baseline: 1.4057x; 1.0928x over previous
#include <cuda_runtime.h>
#include <cuda_bf16.h>
#include <cstdint>
#include <math.h>

// Problem constants
#define M_TOT 4096      // 2*N*T
#define DIM   512
#define TSPAN 16
#define NEG_INV (1.0f/31.0f)

// Device scratch (no allocs allowed)
__device__ __nv_bfloat16 g_znb[M_TOT * DIM];   // normalized z, bf16 (4 MB)
__device__ float g_rowExp[M_TOT];
__device__ float g_rowNum[M_TOT];

// ---------------------------------------------------------------------------
// helpers
// ---------------------------------------------------------------------------
__device__ __forceinline__ uint32_t smem_u32(const void* p) {
    return (uint32_t)__cvta_generic_to_shared(p);
}
__device__ __forceinline__ void ldsm4(uint32_t addr, uint32_t* r) {
    asm volatile("ldmatrix.sync.aligned.m8n8.x4.shared.b16 {%0,%1,%2,%3}, [%4];"
                 : "=r"(r[0]), "=r"(r[1]), "=r"(r[2]), "=r"(r[3]) : "r"(addr));
}
__device__ __forceinline__ void mma16816(float* c, const uint32_t* a, uint32_t b0, uint32_t b1) {
    asm volatile("mma.sync.aligned.m16n8k16.row.col.f32.bf16.bf16.f32 "
                 "{%0,%1,%2,%3}, {%4,%5,%6,%7}, {%8,%9}, {%0,%1,%2,%3};"
                 : "+f"(c[0]), "+f"(c[1]), "+f"(c[2]), "+f"(c[3])
                 : "r"(a[0]), "r"(a[1]), "r"(a[2]), "r"(a[3]), "r"(b0), "r"(b1));
}
#define CP_ASYNC16(dst, src) \
    asm volatile("cp.async.cg.shared.global [%0], [%1], 16;\n" :: "r"(dst), "l"(src))
#define CP_COMMIT() asm volatile("cp.async.commit_group;\n" ::: "memory")
#define CP_WAIT2()  asm volatile("cp.async.wait_group 2;\n" ::: "memory")

// FFMA-only exp(10*a): 2^(a*14.4269504), degree-5 poly on [-0.5, 0.5]
__device__ __forceinline__ float exp10x(float a) {
    const float L = 14.4269504f;
    const float tk = __fmaf_rn(a, L, 12582912.0f);
    const int   X  = __float_as_int(tk);
    const float kf = tk - 12582912.0f;
    const float f  = __fmaf_rn(a, L, -kf);
    float p = 1.3333558e-3f;
    p = __fmaf_rn(p, f, 9.6181291e-3f);
    p = __fmaf_rn(p, f, 5.5504109e-2f);
    p = __fmaf_rn(p, f, 2.4022651e-1f);
    p = __fmaf_rn(p, f, 6.9314718e-1f);
    p = __fmaf_rn(p, f, 1.0f);
    return p * __int_as_float((X << 23) + 0x3F800000);
}

// ---------------------------------------------------------------------------
// Kernel 1 (fused prep + groupnum), 1024 threads: warp w <-> group row w.
// (unchanged — proven)
// ---------------------------------------------------------------------------
#define PREP_SMEM ((32 * DIM + 2 * DIM) * 4)   // 64KB + 4KB

__global__ void __launch_bounds__(1024) prep_kernel(const float* __restrict__ z) {
    extern __shared__ float sm[];
    float* sZ = sm;                  // [32][DIM]
    float* SP = sm + 32 * DIM;       // [2][DIM] partial group sums
    const int grp = blockIdx.x, tid = threadIdx.x;
    const int wid = tid >> 5, lane = tid & 31;

    const int row = grp * TSPAN + (wid & 15) + (wid >> 4) * (M_TOT / 2);
    {
        const float4* src = (const float4*)(z + (size_t)row * DIM);
        float4 v[4]; float ss = 0.f;
        #pragma unroll
        for (int k = 0; k < 4; ++k) {
            v[k] = src[lane + k * 32];
            ss += v[k].x*v[k].x + v[k].y*v[k].y + v[k].z*v[k].z + v[k].w*v[k].w;
        }
        #pragma unroll
        for (int o = 16; o; o >>= 1) ss += __shfl_xor_sync(0xffffffffu, ss, o);
        const float rn = 1.0f / fmaxf(sqrtf(ss), 1e-8f);
        __nv_bfloat162* dst = (__nv_bfloat162*)(g_znb + (size_t)row * DIM);
        float4* srow = (float4*)(sZ + wid * DIM);
        #pragma unroll
        for (int k = 0; k < 4; ++k) {
            const int idx = lane + k * 32;
            float4 x;
            x.x = v[k].x*rn; x.y = v[k].y*rn; x.z = v[k].z*rn; x.w = v[k].w*rn;
            srow[idx] = x;
            dst[idx*2 + 0] = __floats2bfloat162_rn(x.x, x.y);
            dst[idx*2 + 1] = __floats2bfloat162_rn(x.z, x.w);
        }
    }
    if (lane == 0) g_rowExp[row] = 0.f;
    __syncthreads();

    {
        const int d = tid & (DIM - 1);
        const int half = tid >> 9;           // 0 or 1
        float s = 0.f;
        #pragma unroll
        for (int r = 0; r < 16; ++r) s += sZ[(half * 16 + r) * DIM + d];
        SP[half * DIM + d] = s;
    }
    __syncthreads();

    {
        float d1 = 0.f, d2 = 0.f;
        const float4* zr  = (const float4*)(sZ + wid * DIM);
        const float4* s0  = (const float4*)SP;
        const float4* s1  = (const float4*)(SP + DIM);
        #pragma unroll
        for (int j = 0; j < 4; ++j) {
            const float4 a  = zr[lane + j * 32];
            const float4 p0 = s0[lane + j * 32];
            const float4 p1 = s1[lane + j * 32];
            d1 += a.x*(p0.x+p1.x) + a.y*(p0.y+p1.y) + a.z*(p0.z+p1.z) + a.w*(p0.w+p1.w);
            d2 += a.x*a.x + a.y*a.y + a.z*a.z + a.w*a.w;
        }
        #pragma unroll
        for (int o = 16; o; o >>= 1) {
            d1 += __shfl_xor_sync(0xffffffffu, d1, o);
            d2 += __shfl_xor_sync(0xffffffffu, d2, o);
        }
        if (lane == 0) g_rowNum[row] = 10.0f * (d1 - d2);
    }
}

// ---------------------------------------------------------------------------
// Kernel 2: bf16 symmetric fused GEMM + exp-sum.
// 528 upper-triangular 128x128 tiles, 512 threads (16 warps, 32x32 warp
// tiles). 3-stage cp.async pipeline, K-chunks of 64.
// ---------------------------------------------------------------------------
#define BT 128
#define KC 64
#define NCHUNK (DIM / KC)                  // 8
#define STAGE_BYTES 32768                  // A 16KB + B 16KB per stage
#define SMEM_BYTES  (3 * STAGE_BYTES)      // 98304

__global__ void __launch_bounds__(512, 2) gemm_kernel() {
    extern __shared__ __align__(16) unsigned char smem[];
    __shared__ float sRow[BT], sCol[BT];

    // Decode upper-triangular tile index: f(b) = b*(65-b)/2
    int idx = blockIdx.x;
    int bi = (int)(32.5f - sqrtf(1056.25f - 2.0f * (float)idx));
    if (bi < 0) bi = 0; if (bi > 31) bi = 31;
    while (bi * (65 - bi) / 2 > idx) --bi;
    while ((bi + 1) * (64 - bi) / 2 <= idx) ++bi;
    const int bj = bi + (idx - bi * (65 - bi) / 2);
    const bool diag = (bi == bj);
    const int rowBase = bi * BT, colBase = bj * BT;

    const int tid = threadIdx.x, lane = tid & 31, wid = tid >> 5;
    const int warp_m = wid & 3;        // 4 x 32 rows
    const int warp_n = wid >> 2;       // 4 x 32 cols
    const uint32_t sbase = smem_u32(smem);

    if (tid < BT) { sRow[tid] = 0.f; sCol[tid] = 0.f; }

    // Loader: 4 threads per row, 2 x 16B units each; swizzled 128B rows
    const int lr = tid >> 2;                    // 0..127
    const int lu = (tid & 3) * 2;               // 0,2,4,6
    const __nv_bfloat16* gA = g_znb + (size_t)(rowBase + lr) * DIM + lu * 8;
    const __nv_bfloat16* gB = g_znb + (size_t)(colBase + lr) * DIM + lu * 8;
    uint32_t dstU[2];
    #pragma unroll
    for (int u = 0; u < 2; ++u)
        dstU[u] = sbase + lr * 128 + (((lu + u) ^ (lr & 7)) << 4);

    // Per-warp ldsm lane-row bases
    const int mrowA = warp_m * 32 + (lane & 15);                       // + mt*16
    const int uA_half = lane >> 4;                                     // ks*2 + this
    const int nrowB = warp_n * 32 + ((lane >> 4) << 3) + (lane & 7);   // + np*16
    const int uB_half = (lane >> 3) & 1;

    float acc[2][4][4];
    #pragma unroll
    for (int a = 0; a < 2; ++a)
        #pragma unroll
        for (int b = 0; b < 4; ++b)
            #pragma unroll
            for (int i = 0; i < 4; ++i) acc[a][b][i] = 0.f;

    // Prologue: stage chunks 0, 1
    #pragma unroll
    for (int s = 0; s < 2; ++s) {
        const uint32_t so = s * STAGE_BYTES;
        #pragma unroll
        for (int u = 0; u < 2; ++u) CP_ASYNC16(dstU[u] + so,         gA + s * KC + u * 8);
        #pragma unroll
        for (int u = 0; u < 2; ++u) CP_ASYNC16(dstU[u] + so + 16384, gB + s * KC + u * 8);
        CP_COMMIT();
    }

    // Main loop: prefetch first, commit every iter, wait_group 2.
    for (int ch = 0; ch < NCHUNK; ++ch) {
        if (ch + 2 < NCHUNK) {
            const uint32_t so = ((ch + 2) % 3) * STAGE_BYTES;
            #pragma unroll
            for (int u = 0; u < 2; ++u) CP_ASYNC16(dstU[u] + so,         gA + (ch + 2) * KC + u * 8);
            #pragma unroll
            for (int u = 0; u < 2; ++u) CP_ASYNC16(dstU[u] + so + 16384, gB + (ch + 2) * KC + u * 8);
        }
        CP_COMMIT();            // every iter -> uniform wait bound
        CP_WAIT2();             // chunk ch resident
        __syncthreads();

        const uint32_t Ab = sbase + (ch % 3) * STAGE_BYTES;
        const uint32_t Bb = Ab + 16384;
        #pragma unroll
        for (int ks = 0; ks < 4; ++ks) {
            uint32_t afr[2][4], bfr[2][4];
            const int u = ks * 2 + uA_half;
            #pragma unroll
            for (int mt = 0; mt < 2; ++mt) {
                const int m = mrowA + mt * 16;
                ldsm4(Ab + m * 128 + ((u ^ (m & 7)) << 4), afr[mt]);
            }
            const int ub = ks * 2 + uB_half;
            #pragma unroll
            for (int np = 0; np < 2; ++np) {
                const int n = nrowB + np * 16;
                ldsm4(Bb + n * 128 + ((ub ^ (n & 7)) << 4), bfr[np]);
            }
            #pragma unroll
            for (int mt = 0; mt < 2; ++mt)
                #pragma unroll
                for (int np = 0; np < 2; ++np) {
                    mma16816(acc[mt][np * 2 + 0], afr[mt], bfr[np][0], bfr[np][1]);
                    mma16816(acc[mt][np * 2 + 1], afr[mt], bfr[np][2], bfr[np][3]);
                }
        }
        __syncthreads();        // protect stage about to be overwritten
    }

    // ---- Epilogue: exp + row sums (and col sums for off-diagonal tiles) ----
    const int gq = lane >> 2, tq = lane & 3;
    float accRow[2][2], accCol[4][2];
    #pragma unroll
    for (int a = 0; a < 2; ++a) { accRow[a][0] = accRow[a][1] = 0.f; }
    #pragma unroll
    for (int a = 0; a < 4; ++a) { accCol[a][0] = accCol[a][1] = 0.f; }

    #pragma unroll
    for (int mt = 0; mt < 2; ++mt)
        #pragma unroll
        for (int nn = 0; nn < 4; ++nn)
            #pragma unroll
            for (int i = 0; i < 4; ++i) {
                float e = exp10x(acc[mt][nn][i]);
                if (diag) {
                    const int dR = warp_m * 32 + mt * 16 + gq + (i >> 1) * 8;
                    const int dC = warp_n * 32 + nn * 8 + tq * 2 + (i & 1);
                    if (dR == dC) e = 0.f;
                }
                accRow[mt][i >> 1] += e;
                accCol[nn][i & 1]  += e;
            }

    #pragma unroll
    for (int o = 1; o <= 2; o <<= 1)
        #pragma unroll
        for (int mt = 0; mt < 2; ++mt) {
            accRow[mt][0] += __shfl_xor_sync(0xffffffffu, accRow[mt][0], o);
            accRow[mt][1] += __shfl_xor_sync(0xffffffffu, accRow[mt][1], o);
        }
    if (!diag) {
        #pragma unroll
        for (int o = 4; o <= 16; o <<= 1)
            #pragma unroll
            for (int nn = 0; nn < 4; ++nn) {
                accCol[nn][0] += __shfl_xor_sync(0xffffffffu, accCol[nn][0], o);
                accCol[nn][1] += __shfl_xor_sync(0xffffffffu, accCol[nn][1], o);
            }
    }

    // sRow/sCol were zeroed at kernel entry; last mainloop sync ordered it.
    if (tq == 0) {
        #pragma unroll
        for (int mt = 0; mt < 2; ++mt)
            #pragma unroll
            for (int ih = 0; ih < 2; ++ih)
                atomicAdd(&sRow[warp_m * 32 + mt * 16 + gq + ih * 8], accRow[mt][ih]);
    }
    if (!diag && gq == 0) {
        #pragma unroll
        for (int nn = 0; nn < 4; ++nn)
            #pragma unroll
            for (int j = 0; j < 2; ++j)
                atomicAdd(&sCol[warp_n * 32 + nn * 8 + tq * 2 + j], accCol[nn][j]);
    }
    __syncthreads();
    if (tid < BT) {
        atomicAdd(&g_rowExp[rowBase + tid], sRow[tid]);
        if (!diag) atomicAdd(&g_rowExp[colBase + tid], sCol[tid]);
    }
}

// ---------------------------------------------------------------------------
// Kernel 3: per-row loss + global mean (separate launch; cheap)
// ---------------------------------------------------------------------------
__global__ void finalize_kernel(float* __restrict__ out) {
    int tid = threadIdx.x;   // 1024 threads
    float s = 0.f;
    #pragma unroll
    for (int k = 0; k < 4; ++k) {
        int r = tid + k * 1024;
        s += g_rowNum[r] * NEG_INV - __logf(g_rowExp[r]);
    }
    #pragma unroll
    for (int o = 16; o; o >>= 1) s += __shfl_xor_sync(0xffffffffu, s, o);
    __shared__ float ws[32];
    if ((tid & 31) == 0) ws[tid >> 5] = s;
    __syncthreads();
    if (tid < 32) {
        float v = ws[tid];
        #pragma unroll
        for (int o = 16; o; o >>= 1) v += __shfl_xor_sync(0xffffffffu, v, o);
        if (tid == 0) out[0] = -v / (float)M_TOT;
    }
}

// ---------------------------------------------------------------------------
extern "C" void kernel_launch(void* const* d_in, const int* in_sizes, int n_in,
                              void* d_out, int out_size) {
    const float* z = (const float*)d_in[0];
    if (n_in > 1 && in_sizes[0] != M_TOT * DIM) z = (const float*)d_in[1];

    cudaFuncSetAttribute(prep_kernel, cudaFuncAttributeMaxDynamicSharedMemorySize, PREP_SMEM);
    cudaFuncSetAttribute(gemm_kernel, cudaFuncAttributeMaxDynamicSharedMemorySize, SMEM_BYTES);

    prep_kernel<<<128, 1024, PREP_SMEM>>>(z);
    gemm_kernel<<<528, 512, SMEM_BYTES>>>();
    finalize_kernel<<<1, 1024>>>((float*)d_out);
}